// round 1
// baseline (speedup 1.0000x reference)
#include <cuda_runtime.h>
#include <cuda_bf16.h>
#include <math.h>

// Problem constants
#define BATCH 2
#define SEQ   2048
#define DMODEL 1024
#define NHEADS 16
#define HDIM  64
#define DHALF 32
#define MROWS (BATCH*SEQ)   // 4096

// ---------------------------------------------------------------------------
// Scratch (device globals; no allocations allowed)
// ---------------------------------------------------------------------------
__device__ float g_q[BATCH*NHEADS*SEQ*HDIM];   // [b,h,s,dh]
__device__ float g_k[BATCH*NHEADS*SEQ*HDIM];
__device__ float g_v[BATCH*NHEADS*SEQ*HDIM];
__device__ float g_attn[BATCH*SEQ*DMODEL];     // [b,s,d]
__device__ float g_cos[SEQ*DHALF];
__device__ float g_sin[SEQ*DHALF];

// ---------------------------------------------------------------------------
// Kernel 0: RoPE table. fp64 phase computation so accuracy survives
// --use_fast_math (fast __cosf has poor argument reduction at |x|~2000).
// ---------------------------------------------------------------------------
__global__ void rope_table_kernel(const int* __restrict__ pos)
{
    int idx = blockIdx.x * blockDim.x + threadIdx.x;
    if (idx >= SEQ * DHALF) return;
    int s = idx / DHALF;
    int i = idx % DHALF;
    double inv = pow(10000.0, -(double)i / (double)DHALF);
    double ang = (double)pos[s] * inv;
    g_cos[idx] = (float)cos(ang);
    g_sin[idx] = (float)sin(ang);
}

// ---------------------------------------------------------------------------
// Kernel 1: fused QKV projection + RoPE epilogue.
// C[m][n] = sum_k A[m][k] * W[n][k]   (einsum 'bsd,ed->bse' => x @ W^T)
// Tile 128x128x8, 256 threads, 8x8 per thread.
// blockIdx.z selects Q/K/V; Q,K get RoPE; outputs in [b,h,s,dh] layout.
// ---------------------------------------------------------------------------
__global__ __launch_bounds__(256) void gemm_qkv_kernel(
    const float* __restrict__ x,
    const float* __restrict__ Wq,
    const float* __restrict__ Wk,
    const float* __restrict__ Wv)
{
    const int z = blockIdx.z;
    const float* __restrict__ W = (z == 0) ? Wq : (z == 1) ? Wk : Wv;

    __shared__ float As[8][128];
    __shared__ float Bs[8][128];

    const int tid = threadIdx.x;
    const int tx = tid & 15;
    const int ty = tid >> 4;
    const int m0 = blockIdx.y * 128;
    const int n0 = blockIdx.x * 128;

    const int lrow = tid >> 1;        // 0..127
    const int lk   = (tid & 1) * 4;   // 0 or 4

    float acc[8][8];
#pragma unroll
    for (int i = 0; i < 8; i++)
#pragma unroll
        for (int j = 0; j < 8; j++) acc[i][j] = 0.0f;

    for (int k0 = 0; k0 < DMODEL; k0 += 8) {
        float4 av = *(const float4*)(x + (m0 + lrow) * DMODEL + k0 + lk);
        float4 bv = *(const float4*)(W + (n0 + lrow) * DMODEL + k0 + lk);
        __syncthreads();
        As[lk+0][lrow] = av.x; As[lk+1][lrow] = av.y;
        As[lk+2][lrow] = av.z; As[lk+3][lrow] = av.w;
        Bs[lk+0][lrow] = bv.x; Bs[lk+1][lrow] = bv.y;
        Bs[lk+2][lrow] = bv.z; Bs[lk+3][lrow] = bv.w;
        __syncthreads();
#pragma unroll
        for (int k = 0; k < 8; k++) {
            float a[8], b[8];
            *(float4*)(a)     = *(const float4*)&As[k][ty * 8];
            *(float4*)(a + 4) = *(const float4*)&As[k][ty * 8 + 4];
            *(float4*)(b)     = *(const float4*)&Bs[k][tx * 8];
            *(float4*)(b + 4) = *(const float4*)&Bs[k][tx * 8 + 4];
#pragma unroll
            for (int i = 0; i < 8; i++)
#pragma unroll
                for (int j = 0; j < 8; j++)
                    acc[i][j] += a[i] * b[j];
        }
    }

    // Epilogue: scatter to [b,h,s,dh], RoPE on Q/K.
#pragma unroll
    for (int i = 0; i < 8; i++) {
        int m = m0 + ty * 8 + i;
        int b = m >> 11;          // /2048
        int s = m & 2047;
#pragma unroll
        for (int j = 0; j < 8; j += 2) {
            int n  = n0 + tx * 8 + j;
            int h  = n >> 6;
            int dh = n & 63;
            float e = acc[i][j];
            float o = acc[i][j + 1];
            int off = (((b * NHEADS + h) * SEQ + s) * HDIM) + dh;
            if (z < 2) {
                int p = dh >> 1;
                float c  = g_cos[s * DHALF + p];
                float sn = g_sin[s * DHALF + p];
                float re = e * c - o * sn;
                float ro = e * sn + o * c;
                float* dst = (z == 0) ? g_q : g_k;
                float2 val = make_float2(re, ro);
                *(float2*)(dst + off) = val;
            } else {
                float2 val = make_float2(e, o);
                *(float2*)(g_v + off) = val;
            }
        }
    }
}

// ---------------------------------------------------------------------------
// Kernel 2: causal flash attention per (b,h).
// 64-query tile, 32-key tiles, online softmax, P staged via smem.
// 256 threads = (tx 0..15, ty 0..15); scores: 4q x 2k per thread;
// O accum: 4q x 4dh per thread.
// ---------------------------------------------------------------------------
__global__ __launch_bounds__(256) void attn_kernel()
{
    const int bh = blockIdx.y;                       // 0..31
    const int qt = gridDim.x - 1 - blockIdx.x;       // heavy tiles first
    const int q0 = qt * 64;

    const float* __restrict__ Q = g_q + (size_t)bh * SEQ * HDIM;
    const float* __restrict__ K = g_k + (size_t)bh * SEQ * HDIM;
    const float* __restrict__ V = g_v + (size_t)bh * SEQ * HDIM;

    __shared__ float Qs[64][65];
    __shared__ float Ks[32][65];
    __shared__ float Vs[32][65];
    __shared__ float Ps[64][33];

    const int tid = threadIdx.x;
    const int tx = tid & 15;
    const int ty = tid >> 4;

    // Load Q tile (64x64)
    for (int t = tid; t < 64 * 16; t += 256) {
        int r = t >> 4, c4 = (t & 15) * 4;
        float4 v = *(const float4*)(Q + (q0 + r) * HDIM + c4);
        Qs[r][c4+0] = v.x; Qs[r][c4+1] = v.y; Qs[r][c4+2] = v.z; Qs[r][c4+3] = v.w;
    }

    float o[4][4];
    float mrow[4], lrow[4];
#pragma unroll
    for (int i = 0; i < 4; i++) {
        mrow[i] = -INFINITY; lrow[i] = 0.0f;
#pragma unroll
        for (int j = 0; j < 4; j++) o[i][j] = 0.0f;
    }

    const float scale = 0.125f;  // 1/sqrt(64)
    const int kmax = q0 + 64;

    for (int k0 = 0; k0 < kmax; k0 += 32) {
        __syncthreads();
        // Load K,V tiles (32x64)
        for (int t = tid; t < 32 * 16; t += 256) {
            int r = t >> 4, c4 = (t & 15) * 4;
            float4 kv = *(const float4*)(K + (k0 + r) * HDIM + c4);
            Ks[r][c4+0] = kv.x; Ks[r][c4+1] = kv.y; Ks[r][c4+2] = kv.z; Ks[r][c4+3] = kv.w;
            float4 vv = *(const float4*)(V + (k0 + r) * HDIM + c4);
            Vs[r][c4+0] = vv.x; Vs[r][c4+1] = vv.y; Vs[r][c4+2] = vv.z; Vs[r][c4+3] = vv.w;
        }
        __syncthreads();

        // Scores: 4q x 2k per thread
        float sc[4][2] = {{0,0},{0,0},{0,0},{0,0}};
#pragma unroll 8
        for (int d = 0; d < 64; d++) {
            float kk0 = Ks[tx * 2 + 0][d];
            float kk1 = Ks[tx * 2 + 1][d];
#pragma unroll
            for (int i = 0; i < 4; i++) {
                float q = Qs[ty * 4 + i][d];
                sc[i][0] += q * kk0;
                sc[i][1] += q * kk1;
            }
        }
        // Scale + causal mask
#pragma unroll
        for (int i = 0; i < 4; i++) {
            int gq = q0 + ty * 4 + i;
#pragma unroll
            for (int j = 0; j < 2; j++) {
                int gk = k0 + tx * 2 + j;
                sc[i][j] = (gk <= gq) ? sc[i][j] * scale : -INFINITY;
            }
        }
        // Online softmax update per row
#pragma unroll
        for (int i = 0; i < 4; i++) {
            float m = fmaxf(sc[i][0], sc[i][1]);
#pragma unroll
            for (int off = 8; off >= 1; off >>= 1)
                m = fmaxf(m, __shfl_xor_sync(0xffffffff, m, off));
            float mn = fmaxf(mrow[i], m);
            float p0 = __expf(sc[i][0] - mn);
            float p1 = __expf(sc[i][1] - mn);
            float ps = p0 + p1;
#pragma unroll
            for (int off = 8; off >= 1; off >>= 1)
                ps += __shfl_xor_sync(0xffffffff, ps, off);
            float alpha = __expf(mrow[i] - mn);
            lrow[i] = lrow[i] * alpha + ps;
            mrow[i] = mn;
#pragma unroll
            for (int j = 0; j < 4; j++) o[i][j] *= alpha;
            Ps[ty * 4 + i][tx * 2 + 0] = p0;
            Ps[ty * 4 + i][tx * 2 + 1] = p1;
        }
        __syncthreads();
        // O += P @ V  (64x32 * 32x64), 4q x 4dh per thread
#pragma unroll 8
        for (int k = 0; k < 32; k++) {
            float vv[4];
#pragma unroll
            for (int j = 0; j < 4; j++) vv[j] = Vs[k][tx * 4 + j];
#pragma unroll
            for (int i = 0; i < 4; i++) {
                float p = Ps[ty * 4 + i][k];
#pragma unroll
                for (int j = 0; j < 4; j++) o[i][j] += p * vv[j];
            }
        }
    }

    // Epilogue: normalize + write [b, s, h*64+dh]
    const int b = bh >> 4;
    const int h = bh & 15;
#pragma unroll
    for (int i = 0; i < 4; i++) {
        int s = q0 + ty * 4 + i;
        float inv = 1.0f / lrow[i];
        float4 val = make_float4(o[i][0]*inv, o[i][1]*inv, o[i][2]*inv, o[i][3]*inv);
        *(float4*)(g_attn + ((size_t)(b * SEQ + s)) * DMODEL + h * HDIM + tx * 4) = val;
    }
}

// ---------------------------------------------------------------------------
// Kernel 3: output projection  out[m][n] = sum_k attn[m][k] * Wo[n][k]
// Same 128x128x8 SGEMM as kernel 1, plain epilogue.
// ---------------------------------------------------------------------------
__global__ __launch_bounds__(256) void gemm_out_kernel(
    const float* __restrict__ Wo, float* __restrict__ out)
{
    __shared__ float As[8][128];
    __shared__ float Bs[8][128];

    const int tid = threadIdx.x;
    const int tx = tid & 15;
    const int ty = tid >> 4;
    const int m0 = blockIdx.y * 128;
    const int n0 = blockIdx.x * 128;
    const int lrow = tid >> 1;
    const int lk   = (tid & 1) * 4;

    float acc[8][8];
#pragma unroll
    for (int i = 0; i < 8; i++)
#pragma unroll
        for (int j = 0; j < 8; j++) acc[i][j] = 0.0f;

    for (int k0 = 0; k0 < DMODEL; k0 += 8) {
        float4 av = *(const float4*)(g_attn + (size_t)(m0 + lrow) * DMODEL + k0 + lk);
        float4 bv = *(const float4*)(Wo + (size_t)(n0 + lrow) * DMODEL + k0 + lk);
        __syncthreads();
        As[lk+0][lrow] = av.x; As[lk+1][lrow] = av.y;
        As[lk+2][lrow] = av.z; As[lk+3][lrow] = av.w;
        Bs[lk+0][lrow] = bv.x; Bs[lk+1][lrow] = bv.y;
        Bs[lk+2][lrow] = bv.z; Bs[lk+3][lrow] = bv.w;
        __syncthreads();
#pragma unroll
        for (int k = 0; k < 8; k++) {
            float a[8], b[8];
            *(float4*)(a)     = *(const float4*)&As[k][ty * 8];
            *(float4*)(a + 4) = *(const float4*)&As[k][ty * 8 + 4];
            *(float4*)(b)     = *(const float4*)&Bs[k][tx * 8];
            *(float4*)(b + 4) = *(const float4*)&Bs[k][tx * 8 + 4];
#pragma unroll
            for (int i = 0; i < 8; i++)
#pragma unroll
                for (int j = 0; j < 8; j++)
                    acc[i][j] += a[i] * b[j];
        }
    }

#pragma unroll
    for (int i = 0; i < 8; i++) {
        int m = m0 + ty * 8 + i;
        float* row = out + (size_t)m * DMODEL + n0 + tx * 8;
        *(float4*)(row)     = make_float4(acc[i][0], acc[i][1], acc[i][2], acc[i][3]);
        *(float4*)(row + 4) = make_float4(acc[i][4], acc[i][5], acc[i][6], acc[i][7]);
    }
}

// ---------------------------------------------------------------------------
// Launch
// Inputs (metadata order): x, Wq, Wk, Wv, Wo, token_positions(int32)
// ---------------------------------------------------------------------------
extern "C" void kernel_launch(void* const* d_in, const int* in_sizes, int n_in,
                              void* d_out, int out_size)
{
    const float* x  = (const float*)d_in[0];
    const float* Wq = (const float*)d_in[1];
    const float* Wk = (const float*)d_in[2];
    const float* Wv = (const float*)d_in[3];
    const float* Wo = (const float*)d_in[4];
    const int*  pos = (const int*)d_in[5];
    float* out = (float*)d_out;

    // 0) RoPE table
    rope_table_kernel<<<(SEQ * DHALF + 255) / 256, 256>>>(pos);

    // 1) QKV projections + RoPE
    gemm_qkv_kernel<<<dim3(DMODEL / 128, MROWS / 128, 3), 256>>>(x, Wq, Wk, Wv);

    // 2) Causal flash attention
    attn_kernel<<<dim3(SEQ / 64, BATCH * NHEADS), 256>>>();

    // 3) Output projection
    gemm_out_kernel<<<dim3(DMODEL / 128, MROWS / 128), 256>>>(Wo, out);
}

// round 4
// speedup vs baseline: 1.9798x; 1.9798x over previous
#include <cuda_runtime.h>
#include <cuda_fp16.h>
#include <math.h>
#include <stdint.h>

// Problem constants
#define BATCH 2
#define SEQ   2048
#define DMODEL 1024
#define NHEADS 16
#define HDIM  64
#define DHALF 32
#define MROWS (BATCH*SEQ)   // 4096

// Projection GEMM tiling
#define BM 128
#define BN 128
#define BK 16
#define KTILES (DMODEL/BK)  // 64
#define ARS 20              // proj smem row stride in halves (16 + 4 pad)

// Attention smem row stride (halves): 144B rows -> 4-bank step, conflict-free frags
#define KRS 72
#define KVARR (64*KRS)      // halves per K/V array per stage

// ---------------------------------------------------------------------------
// Scratch (device globals; no allocations allowed)
// ---------------------------------------------------------------------------
__device__ __half g_qh[BATCH*NHEADS*SEQ*HDIM];  // [b,h,s,dh] fp16 hi
__device__ __half g_ql[BATCH*NHEADS*SEQ*HDIM];  // fp16 lo
__device__ __half g_kh[BATCH*NHEADS*SEQ*HDIM];
__device__ __half g_kl[BATCH*NHEADS*SEQ*HDIM];
__device__ __half g_vth[BATCH*NHEADS*HDIM*SEQ]; // [b,h,dh,s] transposed
__device__ __half g_vtl[BATCH*NHEADS*HDIM*SEQ];
__device__ float  g_attn[BATCH*SEQ*DMODEL];     // [b,s,d] fp32
__device__ float  g_cos[SEQ*DHALF];
__device__ float  g_sin[SEQ*DHALF];

// ---------------------------------------------------------------------------
// Helpers
// ---------------------------------------------------------------------------
__device__ __forceinline__ uint32_t smem_u32(const void* p) {
    uint32_t a;
    asm("{ .reg .u64 t; cvta.to.shared.u64 t, %1; cvt.u32.u64 %0, t; }" : "=r"(a) : "l"(p));
    return a;
}
#define CP16(dst, src) \
    asm volatile("cp.async.cg.shared.global [%0], [%1], 16;" :: "r"(dst), "l"(src))
#define CP_COMMIT() asm volatile("cp.async.commit_group;" ::: "memory")
#define CP_WAIT1()  asm volatile("cp.async.wait_group 1;"  ::: "memory")
#define CP_WAIT0()  asm volatile("cp.async.wait_group 0;"  ::: "memory")

// HMMA fp16: D(16x8,f32) += A(16x16,f16) * B(16x8,f16). sm_70+ PTX shape (k16: sm_80+).
#define MMA_F16(c, a, b) \
    asm volatile("mma.sync.aligned.m16n8k16.row.col.f32.f16.f16.f32 " \
        "{%0,%1,%2,%3}, {%4,%5,%6,%7}, {%8,%9}, {%0,%1,%2,%3};" \
        : "+f"((c)[0]), "+f"((c)[1]), "+f"((c)[2]), "+f"((c)[3]) \
        : "r"((a)[0]), "r"((a)[1]), "r"((a)[2]), "r"((a)[3]), \
          "r"((b)[0]), "r"((b)[1]))

// Split pair of fp32 into packed half2 hi + half2 lo.
__device__ __forceinline__ void split2(float x, float y, uint32_t& hi, uint32_t& lo) {
    __half hx = __float2half_rn(x), hy = __float2half_rn(y);
    __half lx = __float2half_rn(x - __half2float(hx));
    __half ly = __float2half_rn(y - __half2float(hy));
    __half2 h = __halves2half2(hx, hy);
    __half2 l = __halves2half2(lx, ly);
    hi = *(uint32_t*)&h;
    lo = *(uint32_t*)&l;
}
__device__ __forceinline__ uint32_t lds32(const __half* p) { return *(const uint32_t*)p; }

// ---------------------------------------------------------------------------
// Kernel 0: RoPE table (fp64 phase; survives --use_fast_math).
// ---------------------------------------------------------------------------
__global__ void rope_table_kernel(const int* __restrict__ pos)
{
    int idx = blockIdx.x * blockDim.x + threadIdx.x;
    if (idx >= SEQ * DHALF) return;
    int s = idx / DHALF;
    int i = idx % DHALF;
    double inv = pow(10000.0, -(double)i / (double)DHALF);
    double ang = (double)pos[s] * inv;
    g_cos[idx] = (float)cos(ang);
    g_sin[idx] = (float)sin(ang);
}

// ---------------------------------------------------------------------------
// Split-fp16 3-product mainloop: C[m][n] = sum_k A[m][k]*B[n][k] (fp32 in/out).
// 256 threads, 8 warps 2x4, warp tile 64x32, frag m16n8k16.
// ---------------------------------------------------------------------------
typedef __half ptile_t[BM][ARS];

__device__ __forceinline__ void mma_mainloop_f16(
    const float* __restrict__ aptr, const float* __restrict__ bptr,
    int m0, int n0,
    ptile_t* Ah, ptile_t* Al, ptile_t* Bh, ptile_t* Bl,
    float acc[4][4][4])
{
    const int tid    = threadIdx.x;
    const int lane   = tid & 31;
    const int wid    = tid >> 5;
    const int wm     = wid >> 2;
    const int wn     = wid & 3;
    const int g      = lane >> 2;
    const int t      = lane & 3;
    const int lrow   = tid >> 1;       // 0..127
    const int seg    = (tid & 1) * 8;  // float offset in 16-wide k chunk

#pragma unroll
    for (int mf = 0; mf < 4; mf++)
#pragma unroll
        for (int nf = 0; nf < 4; nf++)
#pragma unroll
            for (int c = 0; c < 4; c++) acc[mf][nf][c] = 0.0f;

    const float* arow = aptr + (size_t)(m0 + lrow) * DMODEL + seg;
    const float* brow = bptr + (size_t)(n0 + lrow) * DMODEL + seg;

    float4 ar0, ar1, br0, br1;
#define LOAD_REGS(kt) do {                         \
        ar0 = *(const float4*)(arow + (kt) * BK);  \
        ar1 = *(const float4*)(arow + (kt) * BK + 4); \
        br0 = *(const float4*)(brow + (kt) * BK);  \
        br1 = *(const float4*)(brow + (kt) * BK + 4); \
    } while (0)

    LOAD_REGS(0);

    for (int kt = 0; kt < KTILES; kt++) {
        const int buf = kt & 1;
        // convert + store current regs
        {
            uint32_t h0,h1,h2,h3,l0,l1,l2,l3;
            split2(ar0.x, ar0.y, h0, l0); split2(ar0.z, ar0.w, h1, l1);
            split2(ar1.x, ar1.y, h2, l2); split2(ar1.z, ar1.w, h3, l3);
            uint2* dh = (uint2*)&Ah[buf][lrow][seg];
            uint2* dl = (uint2*)&Al[buf][lrow][seg];
            dh[0] = make_uint2(h0, h1); dh[1] = make_uint2(h2, h3);
            dl[0] = make_uint2(l0, l1); dl[1] = make_uint2(l2, l3);
            split2(br0.x, br0.y, h0, l0); split2(br0.z, br0.w, h1, l1);
            split2(br1.x, br1.y, h2, l2); split2(br1.z, br1.w, h3, l3);
            uint2* eh = (uint2*)&Bh[buf][lrow][seg];
            uint2* el = (uint2*)&Bl[buf][lrow][seg];
            eh[0] = make_uint2(h0, h1); eh[1] = make_uint2(h2, h3);
            el[0] = make_uint2(l0, l1); el[1] = make_uint2(l2, l3);
        }
        __syncthreads();
        if (kt + 1 < KTILES) LOAD_REGS(kt + 1);

        uint32_t a_h[4][4], a_l[4][4], b_h[4][2], b_l[4][2];
#pragma unroll
        for (int mf = 0; mf < 4; mf++) {
            const __half* p  = &Ah[buf][wm * 64 + mf * 16 + g][2 * t];
            const __half* pl = &Al[buf][wm * 64 + mf * 16 + g][2 * t];
            a_h[mf][0] = lds32(p);
            a_h[mf][1] = lds32(p + 8 * ARS);
            a_h[mf][2] = lds32(p + 8);
            a_h[mf][3] = lds32(p + 8 * ARS + 8);
            a_l[mf][0] = lds32(pl);
            a_l[mf][1] = lds32(pl + 8 * ARS);
            a_l[mf][2] = lds32(pl + 8);
            a_l[mf][3] = lds32(pl + 8 * ARS + 8);
        }
#pragma unroll
        for (int nf = 0; nf < 4; nf++) {
            const __half* p  = &Bh[buf][wn * 32 + nf * 8 + g][2 * t];
            const __half* pl = &Bl[buf][wn * 32 + nf * 8 + g][2 * t];
            b_h[nf][0] = lds32(p);
            b_h[nf][1] = lds32(p + 8);
            b_l[nf][0] = lds32(pl);
            b_l[nf][1] = lds32(pl + 8);
        }
#pragma unroll
        for (int mf = 0; mf < 4; mf++)
#pragma unroll
            for (int nf = 0; nf < 4; nf++) {
                MMA_F16(acc[mf][nf], a_h[mf], b_h[nf]);
                MMA_F16(acc[mf][nf], a_h[mf], b_l[nf]);
                MMA_F16(acc[mf][nf], a_l[mf], b_h[nf]);
            }
        __syncthreads();
    }
#undef LOAD_REGS
}

// ---------------------------------------------------------------------------
// Kernel 1: fused QKV projection + RoPE; writes pre-split fp16 hi/lo.
// Q,K -> [b,h,s,dh]; V -> transposed [b,h,dh,s].
// ---------------------------------------------------------------------------
__global__ __launch_bounds__(256) void gemm_qkv_tc(
    const float* __restrict__ x,
    const float* __restrict__ Wq,
    const float* __restrict__ Wk,
    const float* __restrict__ Wv)
{
    __shared__ __half Ah[2][BM][ARS], Al[2][BM][ARS];
    __shared__ __half Bh[2][BN][ARS], Bl[2][BN][ARS];

    const int z = blockIdx.z;
    const float* __restrict__ W = (z == 0) ? Wq : (z == 1) ? Wk : Wv;
    const int m0 = blockIdx.y * BM;
    const int n0 = blockIdx.x * BN;

    float acc[4][4][4];
    mma_mainloop_f16(x, W, m0, n0, Ah, Al, Bh, Bl, acc);

    const int lane = threadIdx.x & 31;
    const int wid  = threadIdx.x >> 5;
    const int wm   = wid >> 2;
    const int wn   = wid & 3;
    const int g    = lane >> 2;
    const int t    = lane & 3;

#pragma unroll
    for (int mf = 0; mf < 4; mf++) {
#pragma unroll
        for (int ci = 0; ci < 2; ci++) {
            const int m = m0 + wm * 64 + mf * 16 + g + ci * 8;
            const int b = m >> 11;
            const int s = m & 2047;
#pragma unroll
            for (int nf = 0; nf < 4; nf++) {
                const int n  = n0 + wn * 32 + nf * 8 + 2 * t;   // even
                const int h  = n >> 6;
                const int dh = n & 63;
                float e = acc[mf][nf][ci * 2 + 0];
                float o = acc[mf][nf][ci * 2 + 1];
                if (z < 2) {
                    const float cs = g_cos[s * DHALF + (dh >> 1)];
                    const float sn = g_sin[s * DHALF + (dh >> 1)];
                    const float re = e * cs - o * sn;
                    const float ro = e * sn + o * cs;
                    uint32_t hi, lo;
                    split2(re, ro, hi, lo);
                    const size_t off = ((size_t)(b * NHEADS + h) * SEQ + s) * HDIM + dh;
                    if (z == 0) {
                        *(uint32_t*)(g_qh + off) = hi;
                        *(uint32_t*)(g_ql + off) = lo;
                    } else {
                        *(uint32_t*)(g_kh + off) = hi;
                        *(uint32_t*)(g_kl + off) = lo;
                    }
                } else {
                    // V transposed: [b,h,dh,s]
                    __half he = __float2half_rn(e);
                    __half le = __float2half_rn(e - __half2float(he));
                    __half ho = __float2half_rn(o);
                    __half lo_ = __float2half_rn(o - __half2float(ho));
                    const size_t vb = ((size_t)(b * NHEADS + h) * HDIM + dh) * SEQ + s;
                    g_vth[vb] = he;       g_vtl[vb] = le;
                    g_vth[vb + SEQ] = ho; g_vtl[vb + SEQ] = lo_;
                }
            }
        }
    }
}

// ---------------------------------------------------------------------------
// Kernel 2: causal flash attention, split-fp16 3-product MMA.
// 128 threads (4 warps), 64-query tile, 64-key tiles, cp.async double buffer.
// Dynamic smem: 2 stages x {Kh,Kl,Vh,Vl}[64][KRS].
// ---------------------------------------------------------------------------
__global__ __launch_bounds__(128) void attn_mma_kernel()
{
    extern __shared__ __half dsm[];
#define S_KH(st) (dsm + (st) * 4 * KVARR)
#define S_KL(st) (dsm + (st) * 4 * KVARR + KVARR)
#define S_VH(st) (dsm + (st) * 4 * KVARR + 2 * KVARR)
#define S_VL(st) (dsm + (st) * 4 * KVARR + 3 * KVARR)

    const int bh = blockIdx.y;                    // 0..31
    const int qt = gridDim.x - 1 - blockIdx.x;    // heavy tiles first
    const int q0 = qt * 64;

    const int tid  = threadIdx.x;
    const int lane = tid & 31;
    const int w    = tid >> 5;
    const int g    = lane >> 2;
    const int t    = lane & 3;
    const int rw   = w * 16;                      // warp's query-row base in tile

    const size_t qkbase = (size_t)bh * SEQ * HDIM;
    const size_t vbase  = (size_t)bh * HDIM * SEQ;

    // ---- Stage Q tile into stage-0 K buffers, load Q fragments to regs ----
    {
        const int row = tid >> 1;
        const int cs  = (tid & 1) * 32;
        const __half* sh = g_qh + qkbase + (size_t)(q0 + row) * HDIM + cs;
        const __half* sl = g_ql + qkbase + (size_t)(q0 + row) * HDIM + cs;
        uint32_t dh = smem_u32(S_KH(0) + row * KRS + cs);
        uint32_t dl = smem_u32(S_KL(0) + row * KRS + cs);
#pragma unroll
        for (int c = 0; c < 4; c++) {
            CP16(dh + c * 16, sh + c * 8);
            CP16(dl + c * 16, sl + c * 8);
        }
        CP_COMMIT();
        CP_WAIT0();
        __syncthreads();
    }
    uint32_t qfh[4][4], qfl[4][4];
#pragma unroll
    for (int kc = 0; kc < 4; kc++) {
        const __half* p  = S_KH(0) + (rw + g) * KRS + kc * 16 + 2 * t;
        const __half* pl = S_KL(0) + (rw + g) * KRS + kc * 16 + 2 * t;
        qfh[kc][0] = lds32(p);            qfh[kc][1] = lds32(p  + 8 * KRS);
        qfh[kc][2] = lds32(p + 8);        qfh[kc][3] = lds32(p  + 8 * KRS + 8);
        qfl[kc][0] = lds32(pl);           qfl[kc][1] = lds32(pl + 8 * KRS);
        qfl[kc][2] = lds32(pl + 8);       qfl[kc][3] = lds32(pl + 8 * KRS + 8);
    }
    __syncthreads();

    float o[8][4];
#pragma unroll
    for (int i = 0; i < 8; i++)
#pragma unroll
        for (int j = 0; j < 4; j++) o[i][j] = 0.0f;
    float m0r = -INFINITY, m1r = -INFINITY, l0r = 0.0f, l1r = 0.0f;

    const int srow = tid >> 1;
    const int scs  = (tid & 1) * 32;

#define ISSUE_KV(kt, st) do {                                                     \
        const int _k0 = (kt) * 64;                                                \
        const __half* _kh = g_kh  + qkbase + (size_t)(_k0 + srow) * HDIM + scs;   \
        const __half* _kl = g_kl  + qkbase + (size_t)(_k0 + srow) * HDIM + scs;   \
        const __half* _vh = g_vth + vbase  + (size_t)srow * SEQ + _k0 + scs;      \
        const __half* _vl = g_vtl + vbase  + (size_t)srow * SEQ + _k0 + scs;      \
        uint32_t _dkh = smem_u32(S_KH(st) + srow * KRS + scs);                    \
        uint32_t _dkl = smem_u32(S_KL(st) + srow * KRS + scs);                    \
        uint32_t _dvh = smem_u32(S_VH(st) + srow * KRS + scs);                    \
        uint32_t _dvl = smem_u32(S_VL(st) + srow * KRS + scs);                    \
        _Pragma("unroll")                                                         \
        for (int _c = 0; _c < 4; _c++) {                                          \
            CP16(_dkh + _c * 16, _kh + _c * 8);                                   \
            CP16(_dkl + _c * 16, _kl + _c * 8);                                   \
            CP16(_dvh + _c * 16, _vh + _c * 8);                                   \
            CP16(_dvl + _c * 16, _vl + _c * 8);                                   \
        }                                                                         \
        CP_COMMIT();                                                              \
    } while (0)

    ISSUE_KV(0, 0);

    const float scale = 0.125f;  // 1/sqrt(64)
    const int qr0 = q0 + rw + g;
    const int qr1 = qr0 + 8;

    for (int kt = 0; kt <= qt; kt++) {
        const int buf = kt & 1;
        if (kt < qt) ISSUE_KV(kt + 1, buf ^ 1);
        if (kt < qt) CP_WAIT1(); else CP_WAIT0();
        __syncthreads();

        // ---- S = Q @ K^T (3-product) ----
        float sc[8][4];
#pragma unroll
        for (int nf = 0; nf < 8; nf++) {
            sc[nf][0] = sc[nf][1] = sc[nf][2] = sc[nf][3] = 0.0f;
#pragma unroll
            for (int kc = 0; kc < 4; kc++) {
                const __half* pb  = S_KH(buf) + (nf * 8 + g) * KRS + kc * 16 + 2 * t;
                const __half* pbl = S_KL(buf) + (nf * 8 + g) * KRS + kc * 16 + 2 * t;
                uint32_t Bh_[2] = { lds32(pb),  lds32(pb + 8)  };
                uint32_t Bl_[2] = { lds32(pbl), lds32(pbl + 8) };
                MMA_F16(sc[nf], qfh[kc], Bh_);
                MMA_F16(sc[nf], qfh[kc], Bl_);
                MMA_F16(sc[nf], qfl[kc], Bh_);
            }
        }

        // ---- scale + causal mask ----
        const int k0 = kt * 64;
        if (kt == qt) {
#pragma unroll
            for (int nf = 0; nf < 8; nf++) {
                const int col = k0 + nf * 8 + 2 * t;
                sc[nf][0] = (col     <= qr0) ? sc[nf][0] * scale : -INFINITY;
                sc[nf][1] = (col + 1 <= qr0) ? sc[nf][1] * scale : -INFINITY;
                sc[nf][2] = (col     <= qr1) ? sc[nf][2] * scale : -INFINITY;
                sc[nf][3] = (col + 1 <= qr1) ? sc[nf][3] * scale : -INFINITY;
            }
        } else {
#pragma unroll
            for (int nf = 0; nf < 8; nf++) {
                sc[nf][0] *= scale; sc[nf][1] *= scale;
                sc[nf][2] *= scale; sc[nf][3] *= scale;
            }
        }

        // ---- online softmax (rows g and g+8 per thread, quad reduction) ----
        float mx0 = -INFINITY, mx1 = -INFINITY;
#pragma unroll
        for (int nf = 0; nf < 8; nf++) {
            mx0 = fmaxf(mx0, fmaxf(sc[nf][0], sc[nf][1]));
            mx1 = fmaxf(mx1, fmaxf(sc[nf][2], sc[nf][3]));
        }
        mx0 = fmaxf(mx0, __shfl_xor_sync(0xffffffff, mx0, 1));
        mx0 = fmaxf(mx0, __shfl_xor_sync(0xffffffff, mx0, 2));
        mx1 = fmaxf(mx1, __shfl_xor_sync(0xffffffff, mx1, 1));
        mx1 = fmaxf(mx1, __shfl_xor_sync(0xffffffff, mx1, 2));
        const float mn0 = fmaxf(m0r, mx0);
        const float mn1 = fmaxf(m1r, mx1);
        const float al0 = __expf(m0r - mn0);
        const float al1 = __expf(m1r - mn1);
        m0r = mn0; m1r = mn1;

        float s0 = 0.0f, s1 = 0.0f;
#pragma unroll
        for (int nf = 0; nf < 8; nf++) {
            sc[nf][0] = __expf(sc[nf][0] - mn0);
            sc[nf][1] = __expf(sc[nf][1] - mn0);
            sc[nf][2] = __expf(sc[nf][2] - mn1);
            sc[nf][3] = __expf(sc[nf][3] - mn1);
            s0 += sc[nf][0] + sc[nf][1];
            s1 += sc[nf][2] + sc[nf][3];
        }
        s0 += __shfl_xor_sync(0xffffffff, s0, 1);
        s0 += __shfl_xor_sync(0xffffffff, s0, 2);
        s1 += __shfl_xor_sync(0xffffffff, s1, 1);
        s1 += __shfl_xor_sync(0xffffffff, s1, 2);
        l0r = l0r * al0 + s0;
        l1r = l1r * al1 + s1;
#pragma unroll
        for (int i = 0; i < 8; i++) {
            o[i][0] *= al0; o[i][1] *= al0;
            o[i][2] *= al1; o[i][3] *= al1;
        }

        // ---- pack P to fp16 hi/lo A-fragments (free layout match) ----
        uint32_t ph[4][4], pl[4][4];
#pragma unroll
        for (int kc = 0; kc < 4; kc++) {
            split2(sc[2*kc  ][0], sc[2*kc  ][1], ph[kc][0], pl[kc][0]);
            split2(sc[2*kc  ][2], sc[2*kc  ][3], ph[kc][1], pl[kc][1]);
            split2(sc[2*kc+1][0], sc[2*kc+1][1], ph[kc][2], pl[kc][2]);
            split2(sc[2*kc+1][2], sc[2*kc+1][3], ph[kc][3], pl[kc][3]);
        }

        // ---- O += P @ V (3-product), V^T tiles: rows=dh, cols=keys ----
#pragma unroll
        for (int df = 0; df < 8; df++) {
#pragma unroll
            for (int kc = 0; kc < 4; kc++) {
                const __half* pv  = S_VH(buf) + (df * 8 + g) * KRS + kc * 16 + 2 * t;
                const __half* pvl = S_VL(buf) + (df * 8 + g) * KRS + kc * 16 + 2 * t;
                uint32_t Vh_[2] = { lds32(pv),  lds32(pv + 8)  };
                uint32_t Vl_[2] = { lds32(pvl), lds32(pvl + 8) };
                MMA_F16(o[df], ph[kc], Vh_);
                MMA_F16(o[df], ph[kc], Vl_);
                MMA_F16(o[df], pl[kc], Vh_);
            }
        }
        __syncthreads();
    }
#undef ISSUE_KV

    // ---- epilogue: normalize, write g_attn[b, s, h*64+dh] ----
    const int b = bh >> 4;
    const int h = bh & 15;
    const float i0 = 1.0f / l0r;
    const float i1 = 1.0f / l1r;
#pragma unroll
    for (int df = 0; df < 8; df++) {
        const int d = h * HDIM + df * 8 + 2 * t;
        *(float2*)(g_attn + (size_t)(b * SEQ + qr0) * DMODEL + d) =
            make_float2(o[df][0] * i0, o[df][1] * i0);
        *(float2*)(g_attn + (size_t)(b * SEQ + qr1) * DMODEL + d) =
            make_float2(o[df][2] * i1, o[df][3] * i1);
    }
}

// ---------------------------------------------------------------------------
// Kernel 3: output projection (split-fp16 3-product), plain epilogue.
// ---------------------------------------------------------------------------
__global__ __launch_bounds__(256) void gemm_out_tc(
    const float* __restrict__ Wo, float* __restrict__ out)
{
    __shared__ __half Ah[2][BM][ARS], Al[2][BM][ARS];
    __shared__ __half Bh[2][BN][ARS], Bl[2][BN][ARS];

    const int m0 = blockIdx.y * BM;
    const int n0 = blockIdx.x * BN;

    float acc[4][4][4];
    mma_mainloop_f16(g_attn, Wo, m0, n0, Ah, Al, Bh, Bl, acc);

    const int lane = threadIdx.x & 31;
    const int wid  = threadIdx.x >> 5;
    const int wm   = wid >> 2;
    const int wn   = wid & 3;
    const int g    = lane >> 2;
    const int t    = lane & 3;

#pragma unroll
    for (int mf = 0; mf < 4; mf++) {
#pragma unroll
        for (int ci = 0; ci < 2; ci++) {
            const int m = m0 + wm * 64 + mf * 16 + g + ci * 8;
#pragma unroll
            for (int nf = 0; nf < 4; nf++) {
                const int n = n0 + wn * 32 + nf * 8 + 2 * t;
                *(float2*)(out + (size_t)m * DMODEL + n) =
                    make_float2(acc[mf][nf][ci * 2 + 0], acc[mf][nf][ci * 2 + 1]);
            }
        }
    }
}

// ---------------------------------------------------------------------------
// Launch. Inputs: x, Wq, Wk, Wv, Wo, token_positions(int32)
// ---------------------------------------------------------------------------
extern "C" void kernel_launch(void* const* d_in, const int* in_sizes, int n_in,
                              void* d_out, int out_size)
{
    const float* x  = (const float*)d_in[0];
    const float* Wq = (const float*)d_in[1];
    const float* Wk = (const float*)d_in[2];
    const float* Wv = (const float*)d_in[3];
    const float* Wo = (const float*)d_in[4];
    const int*  pos = (const int*)d_in[5];
    float* out = (float*)d_out;

    const int attn_smem = 2 * 4 * KVARR * (int)sizeof(__half);  // 73728
    cudaFuncSetAttribute(attn_mma_kernel,
                         cudaFuncAttributeMaxDynamicSharedMemorySize, attn_smem);

    rope_table_kernel<<<(SEQ * DHALF + 255) / 256, 256>>>(pos);
    gemm_qkv_tc<<<dim3(DMODEL / BN, MROWS / BM, 3), 256>>>(x, Wq, Wk, Wv);
    attn_mma_kernel<<<dim3(SEQ / 64, BATCH * NHEADS), 128, attn_smem>>>();
    gemm_out_tc<<<dim3(DMODEL / BN, MROWS / BM), 256>>>(Wo, out);
}